// round 1
// baseline (speedup 1.0000x reference)
#include <cuda_runtime.h>

#define NN 100000
#define NE 1200000

// Scratch (device globals — no allocation allowed in kernel_launch)
__device__ float GBUF[(size_t)NN * 64];   // g = (h@W)*dinv[src], per layer
__device__ float ABUF[(size_t)NN * 64];   // scatter accumulator (init = g: self-loop folded)
__device__ float A3[(size_t)NN * 16];     // layer-3 accumulator (separate to avoid stride race)
__device__ float DINV[NN];
__device__ int   DEG[NN];
__device__ float GSTATS[32];              // [0..4] x-stats, [8..23] embedding sums

// ---------------------------------------------------------------------------
__global__ void k_zero() {
    int i = blockIdx.x * blockDim.x + threadIdx.x;
    if (i < NN) DEG[i] = 0;
    if (i < 32) GSTATS[i] = 0.0f;
}

__global__ void k_deg(const int* __restrict__ ei) {
    int e = blockIdx.x * blockDim.x + threadIdx.x;
    if (e < NE) atomicAdd(&DEG[ei[NE + e]], 1);
}

// dinv = rsqrt(deg+1); fused global x-feature reductions
__global__ void k_dinv_stats(const float* __restrict__ x) {
    int i = blockIdx.x * blockDim.x + threadIdx.x;
    float s0 = 0.f, s1 = 0.f, s2 = 0.f, s3 = 0.f, s4 = 0.f;
    if (i < NN) {
        DINV[i] = rsqrtf((float)DEG[i] + 1.0f);
        float lam = x[i * 5 + 0], mu = x[i * 5 + 1];
        float c = x[i * 5 + 2], a = x[i * 5 + 3], o = x[i * 5 + 4];
        s0 = c; s1 = a; s2 = o; s3 = lam * c; s4 = mu * c;
    }
    #pragma unroll
    for (int off = 16; off; off >>= 1) {
        s0 += __shfl_down_sync(0xffffffffu, s0, off);
        s1 += __shfl_down_sync(0xffffffffu, s1, off);
        s2 += __shfl_down_sync(0xffffffffu, s2, off);
        s3 += __shfl_down_sync(0xffffffffu, s3, off);
        s4 += __shfl_down_sync(0xffffffffu, s4, off);
    }
    if ((threadIdx.x & 31) == 0) {
        atomicAdd(&GSTATS[0], s0);
        atomicAdd(&GSTATS[1], s1);
        atomicAdd(&GSTATS[2], s2);
        atomicAdd(&GSTATS[3], s3);
        atomicAdd(&GSTATS[4], s4);
    }
}

// Layer 1: g = (x @ W1) * dinv ;  GBUF = ABUF = g
__global__ void k_xw1(const float* __restrict__ x, const float* __restrict__ W1) {
    int t = blockIdx.x * blockDim.x + threadIdx.x;   // exactly NN*64 threads
    int node = t >> 6, j = t & 63;
    const float* xr = x + node * 5;
    float s = xr[0] * __ldg(&W1[j])
            + xr[1] * __ldg(&W1[64 + j])
            + xr[2] * __ldg(&W1[128 + j])
            + xr[3] * __ldg(&W1[192 + j])
            + xr[4] * __ldg(&W1[256 + j]);
    float g = s * DINV[node];
    GBUF[node * 64 + j] = g;
    ABUF[node * 64 + j] = g;
}

// Edge scatter, 64-wide: 16 threads/edge, float4 + vectorized red
__global__ void k_scatter64(const int* __restrict__ ei) {
    int t = blockIdx.x * blockDim.x + threadIdx.x;   // exactly NE*16 threads
    int e = t >> 4;
    int c = (t & 15) << 2;
    int src = ei[e], dst = ei[NE + e];
    float4 v = *reinterpret_cast<const float4*>(&GBUF[src * 64 + c]);
    float* p = &ABUF[dst * 64 + c];
    asm volatile("red.global.add.v4.f32 [%0], {%1,%2,%3,%4};"
                 :: "l"(p), "f"(v.x), "f"(v.y), "f"(v.z), "f"(v.w) : "memory");
}

// Layer 2: a = relu(dinv*agg1 + b1); g2 = (a @ W2) * dinv
__global__ void k_layer2(const float* __restrict__ W2, const float* __restrict__ b1) {
    __shared__ float Ws[64 * 64];
    __shared__ float As[4][64];
    int tx = threadIdx.x, ty = threadIdx.y;
    int tid = ty * 64 + tx;
    for (int idx = tid; idx < 64 * 64; idx += 256) Ws[idx] = W2[idx];
    int node = blockIdx.x * 4 + ty;                  // grid = NN/4 exactly
    float di = DINV[node];
    As[ty][tx] = fmaxf(di * ABUF[node * 64 + tx] + b1[tx], 0.0f);
    __syncthreads();
    float s = 0.0f;
    #pragma unroll 16
    for (int k = 0; k < 64; k++) s += As[ty][k] * Ws[k * 64 + tx];
    float g = s * di;
    GBUF[node * 64 + tx] = g;
    ABUF[node * 64 + tx] = g;
}

// Layer 3: a = relu(dinv*agg2 + b2); g3 = (a @ W3) * dinv  (64 -> 16)
__global__ void k_layer3(const float* __restrict__ W3, const float* __restrict__ b2) {
    __shared__ float Ws[64 * 16];
    __shared__ float As[4][64];
    int tx = threadIdx.x, ty = threadIdx.y;
    int tid = ty * 64 + tx;
    for (int idx = tid; idx < 64 * 16; idx += 256) Ws[idx] = W3[idx];
    int node = blockIdx.x * 4 + ty;
    float di = DINV[node];
    As[ty][tx] = fmaxf(di * ABUF[node * 64 + tx] + b2[tx], 0.0f);
    __syncthreads();
    if (tx < 16) {
        float s = 0.0f;
        #pragma unroll 16
        for (int k = 0; k < 64; k++) s += As[ty][k] * Ws[k * 16 + tx];
        float g = s * di;
        GBUF[node * 16 + tx] = g;   // GBUF not read in this kernel: safe overlap
        A3[node * 16 + tx] = g;     // separate buffer: ABUF is still being read
    }
}

// Edge scatter, 16-wide: 4 threads/edge
__global__ void k_scatter16(const int* __restrict__ ei) {
    int t = blockIdx.x * blockDim.x + threadIdx.x;   // exactly NE*4 threads
    int e = t >> 2;
    int c = (t & 3) << 2;
    int src = ei[e], dst = ei[NE + e];
    float4 v = *reinterpret_cast<const float4*>(&GBUF[src * 16 + c]);
    float* p = &A3[dst * 16 + c];
    asm volatile("red.global.add.v4.f32 [%0], {%1,%2,%3,%4};"
                 :: "l"(p), "f"(v.x), "f"(v.y), "f"(v.z), "f"(v.w) : "memory");
}

// Mean over nodes of dinv[i]*agg3[i][:]  (b3 + /N applied in MLP kernel)
__global__ void k_reduce() {
    __shared__ float s[16];
    int tid = threadIdx.x;
    if (tid < 16) s[tid] = 0.0f;
    __syncthreads();
    int t = blockIdx.x * 256 + tid;                  // exactly NN*16 threads
    int node = t >> 4, c = t & 15;
    float v = DINV[node] * A3[node * 16 + c];
    v += __shfl_down_sync(0xffffffffu, v, 16);
    if ((tid & 31) < 16) atomicAdd(&s[c], v);
    __syncthreads();
    if (tid < 16) atomicAdd(&GSTATS[8 + tid], s[tid]);
}

__device__ __forceinline__ float softplusf(float v) {
    return fmaxf(v, 0.0f) + log1pf(expf(-fabsf(v)));
}

// Final MLP head, single block of 64 threads
__global__ void k_mlp(const float* __restrict__ T, const float* __restrict__ Tm,
                      const float* __restrict__ b3,
                      const float* __restrict__ P1, const float* __restrict__ pb1,
                      const float* __restrict__ P2, const float* __restrict__ pb2,
                      const float* __restrict__ P3, const float* __restrict__ pb3,
                      float* __restrict__ out) {
    __shared__ float emb[24], h1[64], h2[32], val[4];
    int tid = threadIdx.x;
    if (tid < 16) emb[tid] = GSTATS[8 + tid] * (1.0f / NN) + b3[tid];
    if (tid == 0) {
        float ncomp = GSTATS[0], nAND = GSTATS[1], nOR = GSTATS[2];
        float slam = GSTATS[3], smu = GSTATS[4];
        float Tn = T[0] / Tm[0];
        float safe = fmaxf(ncomp, 1.0f);
        bool has = ncomp > 0.0f;
        emb[16] = ncomp; emb[17] = nAND; emb[18] = nOR; emb[19] = nAND + nOR;
        emb[20] = has ? slam / safe : 0.0f;
        emb[21] = has ? smu / safe : 0.0f;
        emb[22] = Tn * 50.0f;
        emb[23] = (1.0f / (1.0f + Tn)) * 50.0f;
    }
    __syncthreads();
    {
        float s = pb1[tid];
        #pragma unroll
        for (int k = 0; k < 24; k++) s += emb[k] * P1[k * 64 + tid];
        h1[tid] = fmaxf(s, 0.0f);
    }
    __syncthreads();
    if (tid < 32) {
        float s = pb2[tid];
        #pragma unroll
        for (int k = 0; k < 64; k++) s += h1[k] * P2[k * 32 + tid];
        h2[tid] = fmaxf(s, 0.0f);
    }
    __syncthreads();
    if (tid < 4) {
        float s = pb3[tid];
        #pragma unroll
        for (int k = 0; k < 32; k++) s += h2[k] * P3[k * 4 + tid];
        val[tid] = softplusf(s + 2.0f);
    }
    __syncthreads();
    if (tid == 0) {
        float amin = 1.0f + val[0];
        out[0] = amin;
        out[1] = amin + val[1] + 0.5f;
        float bmin = 1.0f + val[2];
        out[2] = bmin;
        out[3] = bmin + val[3] + 0.5f;
    }
    if (tid < 24) out[4 + tid] = emb[tid];
}

// ---------------------------------------------------------------------------
extern "C" void kernel_launch(void* const* d_in, const int* in_sizes, int n_in,
                              void* d_out, int out_size) {
    const float* x   = (const float*)d_in[0];
    const int*   ei  = (const int*)d_in[1];
    const float* T   = (const float*)d_in[2];
    const float* Tm  = (const float*)d_in[3];
    const float* W1  = (const float*)d_in[4];
    const float* b1  = (const float*)d_in[5];
    const float* W2  = (const float*)d_in[6];
    const float* b2  = (const float*)d_in[7];
    const float* W3  = (const float*)d_in[8];
    const float* b3  = (const float*)d_in[9];
    const float* P1  = (const float*)d_in[10];
    const float* pb1 = (const float*)d_in[11];
    const float* P2  = (const float*)d_in[12];
    const float* pb2 = (const float*)d_in[13];
    const float* P3  = (const float*)d_in[14];
    const float* pb3 = (const float*)d_in[15];
    float* out = (float*)d_out;

    k_zero<<<(NN + 255) / 256, 256>>>();
    k_deg<<<(NE + 255) / 256, 256>>>(ei);
    k_dinv_stats<<<(NN + 255) / 256, 256>>>(x);

    k_xw1<<<NN * 64 / 256, 256>>>(x, W1);            // 25000 blocks exact
    k_scatter64<<<NE * 16 / 256, 256>>>(ei);         // 75000 blocks exact

    dim3 blk(64, 4);
    k_layer2<<<NN / 4, blk>>>(W2, b1);               // 25000 blocks exact
    k_scatter64<<<NE * 16 / 256, 256>>>(ei);

    k_layer3<<<NN / 4, blk>>>(W3, b2);
    k_scatter16<<<NE * 4 / 256, 256>>>(ei);          // 18750 blocks exact

    k_reduce<<<NN * 16 / 256, 256>>>();              // 6250 blocks exact
    k_mlp<<<1, 64>>>(T, Tm, b3, P1, pb1, P2, pb2, P3, pb3, out);
}

// round 2
// speedup vs baseline: 1.5473x; 1.5473x over previous
#include <cuda_runtime.h>
#include <cuda_fp16.h>

#define NN 100000
#define NE 1200000
#define SCAN_B 391   // ceil(NN/256)

// Scratch (device globals — no allocation allowed)
__device__ unsigned HA[(size_t)NN * 32];  // layer-1 g, fp16x2 (64 feats)
__device__ unsigned HB[(size_t)NN * 32];  // layer-2 g, fp16x2
__device__ unsigned H3[(size_t)NN * 8];   // layer-3 g, fp16x2 (16 feats)
__device__ int   ESRC[NE];                // CSR: src ids grouped by dst
__device__ int   ROWP[NN];                // CSR row pointers (exclusive scan of DEG)
__device__ int   DEG[NN];
__device__ int   CUR[NN];
__device__ int   BSUM[SCAN_B];
__device__ float DINV[NN];
__device__ float GSTATS[32];              // [0..4] x-stats, [8..23] embedding sums

// ---------------------------------------------------------------------------
__global__ void k_zero() {
    int i = blockIdx.x * blockDim.x + threadIdx.x;
    if (i < NN) { DEG[i] = 0; CUR[i] = 0; }
    if (i < 32) GSTATS[i] = 0.0f;
}

__global__ void k_deg(const int* __restrict__ ei) {
    int e = blockIdx.x * blockDim.x + threadIdx.x;
    if (e < NE) atomicAdd(&DEG[ei[NE + e]], 1);
}

// dinv = rsqrt(deg+1); fused global x-feature reductions
__global__ void k_dinv_stats(const float* __restrict__ x) {
    int i = blockIdx.x * blockDim.x + threadIdx.x;
    float s0 = 0.f, s1 = 0.f, s2 = 0.f, s3 = 0.f, s4 = 0.f;
    if (i < NN) {
        DINV[i] = rsqrtf((float)DEG[i] + 1.0f);
        float lam = x[i * 5 + 0], mu = x[i * 5 + 1];
        float c = x[i * 5 + 2], a = x[i * 5 + 3], o = x[i * 5 + 4];
        s0 = c; s1 = a; s2 = o; s3 = lam * c; s4 = mu * c;
    }
    #pragma unroll
    for (int off = 16; off; off >>= 1) {
        s0 += __shfl_down_sync(0xffffffffu, s0, off);
        s1 += __shfl_down_sync(0xffffffffu, s1, off);
        s2 += __shfl_down_sync(0xffffffffu, s2, off);
        s3 += __shfl_down_sync(0xffffffffu, s3, off);
        s4 += __shfl_down_sync(0xffffffffu, s4, off);
    }
    if ((threadIdx.x & 31) == 0) {
        atomicAdd(&GSTATS[0], s0);
        atomicAdd(&GSTATS[1], s1);
        atomicAdd(&GSTATS[2], s2);
        atomicAdd(&GSTATS[3], s3);
        atomicAdd(&GSTATS[4], s4);
    }
}

// ---- CSR build: block sums -> scan of block sums -> row pointers -> place
__global__ void k_scanA() {
    int t = threadIdx.x;
    int i = blockIdx.x * 256 + t;
    int v = (i < NN) ? DEG[i] : 0;
    #pragma unroll
    for (int off = 16; off; off >>= 1) v += __shfl_down_sync(0xffffffffu, v, off);
    __shared__ int ws[8];
    if ((t & 31) == 0) ws[t >> 5] = v;
    __syncthreads();
    if (t == 0) {
        int s = 0;
        #pragma unroll
        for (int w = 0; w < 8; w++) s += ws[w];
        BSUM[blockIdx.x] = s;
    }
}

__global__ void k_scanB() {
    __shared__ int s[512];
    int t = threadIdx.x;
    int v = (t < SCAN_B) ? BSUM[t] : 0;
    s[t] = v;
    __syncthreads();
    for (int off = 1; off < 512; off <<= 1) {
        int u = (t >= off) ? s[t - off] : 0;
        __syncthreads();
        s[t] += u;
        __syncthreads();
    }
    if (t < SCAN_B) BSUM[t] = s[t] - v;   // exclusive
}

__global__ void k_scanC() {
    __shared__ int s[256];
    int t = threadIdx.x;
    int i = blockIdx.x * 256 + t;
    int v = (i < NN) ? DEG[i] : 0;
    s[t] = v;
    __syncthreads();
    for (int off = 1; off < 256; off <<= 1) {
        int u = (t >= off) ? s[t - off] : 0;
        __syncthreads();
        s[t] += u;
        __syncthreads();
    }
    if (i < NN) ROWP[i] = BSUM[blockIdx.x] + s[t] - v;
}

__global__ void k_place(const int* __restrict__ ei) {
    int e = blockIdx.x * blockDim.x + threadIdx.x;
    if (e < NE) {
        int dst = ei[NE + e];
        int pos = ROWP[dst] + atomicAdd(&CUR[dst], 1);
        ESRC[pos] = ei[e];
    }
}

// ---------------------------------------------------------------------------
// Layer 1: g1 = (x @ W1) * dinv, stored fp16x2. Warp per node, lane = feat pair.
__global__ void k_xw1(const float* __restrict__ x, const float* __restrict__ W1) {
    __shared__ float2 W1s[160];   // 5 x 64 floats = 160 float2
    int t = threadIdx.x;
    if (t < 160) W1s[t] = ((const float2*)W1)[t];
    __syncthreads();
    int lane = t & 31, w = t >> 5;
    int node = blockIdx.x * 8 + w;
    float xv = (lane < 5) ? x[node * 5 + lane] : 0.0f;
    float2 s = make_float2(0.f, 0.f);
    #pragma unroll
    for (int i = 0; i < 5; i++) {
        float xi = __shfl_sync(0xffffffffu, xv, i);
        float2 wv = W1s[i * 32 + lane];
        s.x += xi * wv.x; s.y += xi * wv.y;
    }
    float di = DINV[node];
    __half2 o = __floats2half2_rn(s.x * di, s.y * di);
    HA[node * 32 + lane] = *(unsigned*)&o;
}

// Gather HA over CSR, relu(di*agg+b1), @ W2, *di -> HB (fp16x2)
__global__ void k_gl2(const float* __restrict__ W2, const float* __restrict__ b1) {
    __shared__ float2 Ws[2048];           // W2 as [64][32] float2
    __shared__ float2 As2[8][32];         // activations, 8 nodes x 64 feats
    int t = threadIdx.x;
    const float2* W2v = (const float2*)W2;
    #pragma unroll
    for (int idx = t; idx < 2048; idx += 256) Ws[idx] = W2v[idx];
    int lane = t & 31, w = t >> 5;
    int node = blockIdx.x * 8 + w;
    int start = ROWP[node], d = DEG[node];
    float di = DINV[node];
    unsigned sv = HA[node * 32 + lane];
    float2 acc = __half22float2(*(__half2*)&sv);
    for (int base = 0; base < d; base += 32) {
        int idx = base + lane;
        int s_l = (idx < d) ? ESRC[start + idx] : 0;
        int m = d - base; if (m > 32) m = 32;
        for (int k = 0; k < m; k++) {
            int s = __shfl_sync(0xffffffffu, s_l, k);
            unsigned v = HA[s * 32 + lane];
            float2 f = __half22float2(*(__half2*)&v);
            acc.x += f.x; acc.y += f.y;
        }
    }
    float2 bb = ((const float2*)b1)[lane];
    As2[w][lane] = make_float2(fmaxf(di * acc.x + bb.x, 0.f),
                               fmaxf(di * acc.y + bb.y, 0.f));
    __syncthreads();
    const float* As = (const float*)As2[w];
    float s0 = 0.f, s1 = 0.f;
    #pragma unroll 16
    for (int k = 0; k < 64; k++) {
        float a = As[k];
        float2 wv = Ws[k * 32 + lane];
        s0 += a * wv.x; s1 += a * wv.y;
    }
    __half2 o = __floats2half2_rn(s0 * di, s1 * di);
    HB[node * 32 + lane] = *(unsigned*)&o;
}

// Gather HB, relu(di*agg+b2), @ W3 (64->16), *di -> H3 (fp16x2)
__global__ void k_gl3(const float* __restrict__ W3, const float* __restrict__ b2) {
    __shared__ float Ws[64 * 16];
    __shared__ float2 As2[8][32];
    int t = threadIdx.x;
    #pragma unroll
    for (int idx = t; idx < 1024; idx += 256) Ws[idx] = W3[idx];
    int lane = t & 31, w = t >> 5;
    int node = blockIdx.x * 8 + w;
    int start = ROWP[node], d = DEG[node];
    float di = DINV[node];
    unsigned sv = HB[node * 32 + lane];
    float2 acc = __half22float2(*(__half2*)&sv);
    for (int base = 0; base < d; base += 32) {
        int idx = base + lane;
        int s_l = (idx < d) ? ESRC[start + idx] : 0;
        int m = d - base; if (m > 32) m = 32;
        for (int k = 0; k < m; k++) {
            int s = __shfl_sync(0xffffffffu, s_l, k);
            unsigned v = HB[s * 32 + lane];
            float2 f = __half22float2(*(__half2*)&v);
            acc.x += f.x; acc.y += f.y;
        }
    }
    float2 bb = ((const float2*)b2)[lane];
    As2[w][lane] = make_float2(fmaxf(di * acc.x + bb.x, 0.f),
                               fmaxf(di * acc.y + bb.y, 0.f));
    __syncthreads();
    const float* As = (const float*)As2[w];
    int j = lane & 15;                    // all lanes compute (upper half duplicates)
    float s = 0.f;
    #pragma unroll 16
    for (int k = 0; k < 64; k++) s += As[k] * Ws[k * 16 + j];
    s *= di;
    float hi = __shfl_xor_sync(0xffffffffu, s, 1);
    if (lane < 16 && !(lane & 1)) {
        __half2 o = __floats2half2_rn(s, hi);
        H3[node * 8 + (j >> 1)] = *(unsigned*)&o;
    }
}

// Final gather of H3 + global mean: 8 lanes per node, 4 nodes per warp
__global__ void k_gr() {
    __shared__ float sbin[16];
    int t = threadIdx.x;
    if (t < 16) sbin[t] = 0.0f;
    __syncthreads();
    int lane = t & 31;
    int u = lane & 7;
    int node = blockIdx.x * 32 + (t >> 3);
    int start = ROWP[node], d = DEG[node];
    float di = DINV[node];
    unsigned sv = H3[node * 8 + u];
    float2 acc = __half22float2(*(__half2*)&sv);
    for (int k = 0; k < d; k++) {
        int s = ESRC[start + k];
        unsigned v = H3[s * 8 + u];
        float2 f = __half22float2(*(__half2*)&v);
        acc.x += f.x; acc.y += f.y;
    }
    acc.x *= di; acc.y *= di;
    // reduce the 4 node-groups of the warp onto lanes 0..7
    acc.x += __shfl_down_sync(0xffffffffu, acc.x, 16);
    acc.y += __shfl_down_sync(0xffffffffu, acc.y, 16);
    acc.x += __shfl_down_sync(0xffffffffu, acc.x, 8);
    acc.y += __shfl_down_sync(0xffffffffu, acc.y, 8);
    if (lane < 8) {
        atomicAdd(&sbin[2 * u], acc.x);
        atomicAdd(&sbin[2 * u + 1], acc.y);
    }
    __syncthreads();
    if (t < 16) atomicAdd(&GSTATS[8 + t], sbin[t]);
}

__device__ __forceinline__ float softplusf(float v) {
    return fmaxf(v, 0.0f) + log1pf(expf(-fabsf(v)));
}

// Final MLP head, single block of 64 threads
__global__ void k_mlp(const float* __restrict__ T, const float* __restrict__ Tm,
                      const float* __restrict__ b3,
                      const float* __restrict__ P1, const float* __restrict__ pb1,
                      const float* __restrict__ P2, const float* __restrict__ pb2,
                      const float* __restrict__ P3, const float* __restrict__ pb3,
                      float* __restrict__ out) {
    __shared__ float emb[24], h1[64], h2[32], val[4];
    int tid = threadIdx.x;
    if (tid < 16) emb[tid] = GSTATS[8 + tid] * (1.0f / NN) + b3[tid];
    if (tid == 0) {
        float ncomp = GSTATS[0], nAND = GSTATS[1], nOR = GSTATS[2];
        float slam = GSTATS[3], smu = GSTATS[4];
        float Tn = T[0] / Tm[0];
        float safe = fmaxf(ncomp, 1.0f);
        bool has = ncomp > 0.0f;
        emb[16] = ncomp; emb[17] = nAND; emb[18] = nOR; emb[19] = nAND + nOR;
        emb[20] = has ? slam / safe : 0.0f;
        emb[21] = has ? smu / safe : 0.0f;
        emb[22] = Tn * 50.0f;
        emb[23] = (1.0f / (1.0f + Tn)) * 50.0f;
    }
    __syncthreads();
    {
        float s = pb1[tid];
        #pragma unroll
        for (int k = 0; k < 24; k++) s += emb[k] * P1[k * 64 + tid];
        h1[tid] = fmaxf(s, 0.0f);
    }
    __syncthreads();
    if (tid < 32) {
        float s = pb2[tid];
        #pragma unroll
        for (int k = 0; k < 64; k++) s += h1[k] * P2[k * 32 + tid];
        h2[tid] = fmaxf(s, 0.0f);
    }
    __syncthreads();
    if (tid < 4) {
        float s = pb3[tid];
        #pragma unroll
        for (int k = 0; k < 32; k++) s += h2[k] * P3[k * 4 + tid];
        val[tid] = softplusf(s + 2.0f);
    }
    __syncthreads();
    if (tid == 0) {
        float amin = 1.0f + val[0];
        out[0] = amin;
        out[1] = amin + val[1] + 0.5f;
        float bmin = 1.0f + val[2];
        out[2] = bmin;
        out[3] = bmin + val[3] + 0.5f;
    }
    if (tid < 24) out[4 + tid] = emb[tid];
}

// ---------------------------------------------------------------------------
extern "C" void kernel_launch(void* const* d_in, const int* in_sizes, int n_in,
                              void* d_out, int out_size) {
    const float* x   = (const float*)d_in[0];
    const int*   ei  = (const int*)d_in[1];
    const float* T   = (const float*)d_in[2];
    const float* Tm  = (const float*)d_in[3];
    const float* W1  = (const float*)d_in[4];
    const float* b1  = (const float*)d_in[5];
    const float* W2  = (const float*)d_in[6];
    const float* b2  = (const float*)d_in[7];
    const float* W3  = (const float*)d_in[8];
    const float* b3  = (const float*)d_in[9];
    const float* P1  = (const float*)d_in[10];
    const float* pb1 = (const float*)d_in[11];
    const float* P2  = (const float*)d_in[12];
    const float* pb2 = (const float*)d_in[13];
    const float* P3  = (const float*)d_in[14];
    const float* pb3 = (const float*)d_in[15];
    float* out = (float*)d_out;

    k_zero<<<(NN + 255) / 256, 256>>>();
    k_deg<<<(NE + 255) / 256, 256>>>(ei);
    k_dinv_stats<<<(NN + 255) / 256, 256>>>(x);

    k_scanA<<<SCAN_B, 256>>>();
    k_scanB<<<1, 512>>>();
    k_scanC<<<SCAN_B, 256>>>();
    k_place<<<(NE + 255) / 256, 256>>>(ei);

    k_xw1<<<NN / 8, 256>>>(x, W1);        // 12500 blocks
    k_gl2<<<NN / 8, 256>>>(W2, b1);       // gather + layer2
    k_gl3<<<NN / 8, 256>>>(W3, b2);       // gather + layer3
    k_gr<<<NN / 32, 256>>>();             // 3125 blocks
    k_mlp<<<1, 64>>>(T, Tm, b3, P1, pb1, P2, pb2, P3, pb3, out);
}